// round 1
// baseline (speedup 1.0000x reference)
#include <cuda_runtime.h>

#define NN 20000
#define EE 320000
#define GG 256

// -------- scratch (static device globals; no runtime allocation) --------
__device__ float g_bufA[NN * 312];
__device__ float g_bufB[NN * 312];
__device__ int   g_cnt[NN];
__device__ int   g_offs[NN + 1];
__device__ int   g_fill[NN];
__device__ int   g_csr[EE];
__device__ float g_dinv[NN];
__device__ float g_pool[GG * 312];
__device__ float g_xc[GG * 512];
__device__ float g_t0[GG * 2048];
__device__ float g_t1[GG * 2048];

// -------- CSR build --------
__global__ void k_count(const int* __restrict__ dst, int* __restrict__ cnt) {
    int e = blockIdx.x * blockDim.x + threadIdx.x;
    if (e < EE) atomicAdd(&cnt[dst[e]], 1);
}

__global__ void k_dinv(const int* __restrict__ cnt, float* __restrict__ dinv) {
    int n = blockIdx.x * blockDim.x + threadIdx.x;
    if (n < NN) dinv[n] = rsqrtf((float)(cnt[n] + 1));  // +1 self loop
}

__global__ void k_scan(const int* __restrict__ cnt, int* __restrict__ offs) {
    const int T = 1024;
    const int IPT = (NN + T - 1) / T;  // 20
    __shared__ int s[T];
    int tid = threadIdx.x;
    int base = tid * IPT;
    int local = 0;
    #pragma unroll
    for (int i = 0; i < IPT; i++) {
        int idx = base + i;
        if (idx < NN) local += cnt[idx];
    }
    s[tid] = local;
    __syncthreads();
    for (int off = 1; off < T; off <<= 1) {
        int v = 0;
        if (tid >= off) v = s[tid - off];
        __syncthreads();
        if (tid >= off) s[tid] += v;
        __syncthreads();
    }
    int run = (tid == 0) ? 0 : s[tid - 1];
    #pragma unroll
    for (int i = 0; i < IPT; i++) {
        int idx = base + i;
        if (idx < NN) { offs[idx] = run; run += cnt[idx]; }
    }
    if (tid == 0) offs[NN] = s[T - 1];
}

__global__ void k_fill(const int* __restrict__ src, const int* __restrict__ dst,
                       const int* __restrict__ offs, int* __restrict__ fill,
                       int* __restrict__ csr) {
    int e = blockIdx.x * blockDim.x + threadIdx.x;
    if (e < EE) {
        int d = dst[e];
        int p = atomicAdd(&fill[d], 1);
        csr[offs[d] + p] = src[e];
    }
}

// -------- aggregation: out[n] = dinv[n] * (sum_{s in N(n)} dinv[s]*h[s] + dinv[n]*h[n])
// one warp per node, lane covers features strided by 32
template <int DIM, int R>
__global__ void k_agg(const float* __restrict__ h, const int* __restrict__ offs,
                      const int* __restrict__ csr, const float* __restrict__ dinv,
                      float* __restrict__ out) {
    int warp = (blockIdx.x * blockDim.x + threadIdx.x) >> 5;
    int lane = threadIdx.x & 31;
    if (warp >= NN) return;
    int n = warp;
    float din = dinv[n];
    float acc[R];
    #pragma unroll
    for (int r = 0; r < R; r++) {
        int f = lane + 32 * r;
        acc[r] = (f < DIM) ? din * h[n * DIM + f] : 0.f;  // self loop (dinv[n]^2 after final scale)
    }
    int e0 = offs[n], e1 = offs[n + 1];
    for (int e = e0; e < e1; e++) {
        int s = csr[e];
        float ds = dinv[s];
        #pragma unroll
        for (int r = 0; r < R; r++) {
            int f = lane + 32 * r;
            if (f < DIM) acc[r] += ds * h[s * DIM + f];
        }
    }
    #pragma unroll
    for (int r = 0; r < R; r++) {
        int f = lane + 32 * r;
        if (f < DIM) out[n * DIM + f] = din * acc[r];
    }
}

// -------- global max pool (values >= 0 after relu; int-bit atomicMax vs 0-init) --------
__global__ void k_pool(const float* __restrict__ h, const int* __restrict__ batch,
                       float* __restrict__ pool) {
    const int CH = 32;
    const int NCH = (NN + CH - 1) / CH;  // 625
    int idx = blockIdx.x * blockDim.x + threadIdx.x;
    if (idx >= NCH * 312) return;
    int f = idx % 312;
    int c = idx / 312;
    int n0 = c * CH;
    int n1 = min(n0 + CH, NN);
    int curb = batch[n0];
    float m = 0.f;
    for (int n = n0; n < n1; n++) {
        int b = batch[n];
        if (b != curb) {
            atomicMax((int*)&pool[curb * 312 + f], __float_as_int(m));
            curb = b;
            m = 0.f;
        }
        m = fmaxf(m, h[n * 312 + f]);
    }
    atomicMax((int*)&pool[curb * 312 + f], __float_as_int(m));
}

// -------- L2 row normalize (cell: [G, 954]) --------
__global__ void k_norm(const float* __restrict__ cell, float* __restrict__ out) {
    int g = blockIdx.x;
    __shared__ float s[256];
    float ss = 0.f;
    for (int j = threadIdx.x; j < 954; j += 256) {
        float v = cell[g * 954 + j];
        ss += v * v;
    }
    s[threadIdx.x] = ss;
    __syncthreads();
    for (int o = 128; o > 0; o >>= 1) {
        if (threadIdx.x < o) s[threadIdx.x] += s[threadIdx.x + o];
        __syncthreads();
    }
    float inv = 1.f / fmaxf(sqrtf(s[0]), 1e-12f);
    for (int j = threadIdx.x; j < 954; j += 256)
        out[g * 954 + j] = cell[g * 954 + j] * inv;
}

// -------- SGEMM: C[M,N] = A[M,K](lda) @ B[K,N] + bias, optional relu, C row-stride ldc
template <bool RELU>
__global__ void k_sgemm(const float* __restrict__ A, int lda,
                        const float* __restrict__ B,
                        const float* __restrict__ bias,
                        float* __restrict__ C, int ldc,
                        int M, int N, int K) {
    const int BM = 64, BN = 64, BK = 16;
    __shared__ float As[BK][BM];
    __shared__ float Bs[BK][BN];
    int m0 = blockIdx.y * BM;
    int n0 = blockIdx.x * BN;
    int tid = threadIdx.x;
    int tx = tid & 15, ty = tid >> 4;
    float acc[4][4] = {};
    for (int k0 = 0; k0 < K; k0 += BK) {
        #pragma unroll
        for (int i = 0; i < 4; i++) {
            int l = tid + 256 * i;
            int r = l >> 4, c = l & 15;
            int mm = m0 + r, kk = k0 + c;
            As[c][r] = (mm < M && kk < K) ? A[mm * lda + kk] : 0.f;
        }
        #pragma unroll
        for (int i = 0; i < 4; i++) {
            int l = tid + 256 * i;
            int r = l >> 6, c = l & 63;
            int kk = k0 + r, nn = n0 + c;
            Bs[r][c] = (kk < K && nn < N) ? B[kk * N + nn] : 0.f;
        }
        __syncthreads();
        #pragma unroll
        for (int kk = 0; kk < BK; kk++) {
            float a[4], b[4];
            #pragma unroll
            for (int i = 0; i < 4; i++) a[i] = As[kk][ty * 4 + i];
            #pragma unroll
            for (int j = 0; j < 4; j++) b[j] = Bs[kk][tx * 4 + j];
            #pragma unroll
            for (int i = 0; i < 4; i++)
                #pragma unroll
                for (int j = 0; j < 4; j++) acc[i][j] += a[i] * b[j];
        }
        __syncthreads();
    }
    #pragma unroll
    for (int i = 0; i < 4; i++) {
        int mm = m0 + ty * 4 + i;
        if (mm >= M) continue;
        #pragma unroll
        for (int j = 0; j < 4; j++) {
            int nn = n0 + tx * 4 + j;
            if (nn >= N) continue;
            float v = acc[i][j] + bias[nn];
            if (RELU) v = fmaxf(v, 0.f);
            C[mm * ldc + nn] = v;
        }
    }
}

static void sgemm(const float* A, int lda, const float* B, const float* bias,
                  float* C, int ldc, int M, int N, int K, bool relu) {
    dim3 grid((N + 63) / 64, (M + 63) / 64);
    if (relu)
        k_sgemm<true><<<grid, 256>>>(A, lda, B, bias, C, ldc, M, N, K);
    else
        k_sgemm<false><<<grid, 256>>>(A, lda, B, bias, C, ldc, M, N, K);
}

extern "C" void kernel_launch(void* const* d_in, const int* in_sizes, int n_in,
                              void* d_out, int out_size) {
    const float* x1   = (const float*)d_in[0];
    const int*   ei1  = (const int*)d_in[1];
    const int*   bat1 = (const int*)d_in[2];
    const float* x2   = (const float*)d_in[3];
    const int*   ei2  = (const int*)d_in[4];
    const int*   bat2 = (const int*)d_in[5];
    const float* cell = (const float*)d_in[6];
    const float* Wc1 = (const float*)d_in[7];  const float* bc1 = (const float*)d_in[8];
    const float* Wc2 = (const float*)d_in[9];  const float* bc2 = (const float*)d_in[10];
    const float* Wc3 = (const float*)d_in[11]; const float* bc3 = (const float*)d_in[12];
    const float* Wg1 = (const float*)d_in[13]; const float* bg1 = (const float*)d_in[14];
    const float* Wg2 = (const float*)d_in[15]; const float* bg2 = (const float*)d_in[16];
    const float* Wr1 = (const float*)d_in[17]; const float* br1 = (const float*)d_in[18];
    const float* Wr2 = (const float*)d_in[19]; const float* br2 = (const float*)d_in[20];
    const float* Wr3 = (const float*)d_in[21]; const float* br3 = (const float*)d_in[22];
    const float* Wf1 = (const float*)d_in[23]; const float* bf1 = (const float*)d_in[24];
    const float* Wf2 = (const float*)d_in[25]; const float* bf2 = (const float*)d_in[26];
    const float* Wf3 = (const float*)d_in[27]; const float* bf3 = (const float*)d_in[28];
    const float* Wo  = (const float*)d_in[29]; const float* bo  = (const float*)d_in[30];
    float* out = (float*)d_out;

    float *bufA, *bufB, *dinv, *pool, *xc, *t0, *t1;
    int *cnt, *offs, *fill, *csr;
    cudaGetSymbolAddress((void**)&bufA, g_bufA);
    cudaGetSymbolAddress((void**)&bufB, g_bufB);
    cudaGetSymbolAddress((void**)&cnt,  g_cnt);
    cudaGetSymbolAddress((void**)&offs, g_offs);
    cudaGetSymbolAddress((void**)&fill, g_fill);
    cudaGetSymbolAddress((void**)&csr,  g_csr);
    cudaGetSymbolAddress((void**)&dinv, g_dinv);
    cudaGetSymbolAddress((void**)&pool, g_pool);
    cudaGetSymbolAddress((void**)&xc,   g_xc);
    cudaGetSymbolAddress((void**)&t0,   g_t0);
    cudaGetSymbolAddress((void**)&t1,   g_t1);

    const int EB = (EE + 255) / 256;
    const int NB = (NN + 255) / 256;
    const int AGGB = (NN * 32 + 255) / 256;  // one warp per node

    for (int br = 0; br < 2; br++) {
        const float* x     = br ? x2 : x1;
        const int*   ei    = br ? ei2 : ei1;
        const int*   batch = br ? bat2 : bat1;
        const int* src = ei;
        const int* dst = ei + EE;

        cudaMemsetAsync(cnt,  0, NN * sizeof(int));
        cudaMemsetAsync(fill, 0, NN * sizeof(int));
        k_count<<<EB, 256>>>(dst, cnt);
        k_dinv<<<NB, 256>>>(cnt, dinv);
        k_scan<<<1, 1024>>>(cnt, offs);
        k_fill<<<EB, 256>>>(src, dst, offs, fill, csr);

        // layer 1: agg(x) @ Wc1 -> relu -> h1 [N,78]
        k_agg<78, 3><<<AGGB, 256>>>(x, offs, csr, dinv, bufA);
        sgemm(bufA, 78, Wc1, bc1, bufB, 78, NN, 78, 78, true);
        // layer 2: agg(h1) @ Wc2 -> relu -> h2 [N,156]
        k_agg<78, 3><<<AGGB, 256>>>(bufB, offs, csr, dinv, bufA);
        sgemm(bufA, 78, Wc2, bc2, bufB, 156, NN, 156, 78, true);
        // layer 3: agg(h2) @ Wc3 -> relu -> h3 [N,312]
        k_agg<156, 5><<<AGGB, 256>>>(bufB, offs, csr, dinv, bufA);
        sgemm(bufA, 156, Wc3, bc3, bufB, 312, NN, 312, 156, true);

        // global max pool -> [G,312]
        cudaMemsetAsync(pool, 0, GG * 312 * sizeof(float));
        int pthreads = ((NN + 31) / 32) * 312;
        k_pool<<<(pthreads + 255) / 256, 256>>>(bufB, batch, pool);

        // branch MLP -> xc columns [br*128 .. br*128+128)
        sgemm(pool, 312, Wg1, bg1, t0, 156, GG, 156, 312, true);
        sgemm(t0, 156, Wg2, bg2, xc + br * 128, 512, GG, 128, 156, false);
    }

    // cell reduction MLP -> xc columns [256..512)
    k_norm<<<GG, 256>>>(cell, t0);                       // t0: [G,954]
    sgemm(t0, 954, Wr1, br1, t1, 2048, GG, 2048, 954, true);
    sgemm(t1, 2048, Wr2, br2, t0, 512, GG, 512, 2048, true);
    sgemm(t0, 512, Wr3, br3, xc + 256, 512, GG, 256, 512, true);

    // head MLP
    sgemm(xc, 512, Wf1, bf1, t0, 1024, GG, 1024, 512, true);
    sgemm(t0, 1024, Wf2, bf2, t1, 512, GG, 512, 1024, true);
    sgemm(t1, 512, Wf3, bf3, t0, 128, GG, 128, 512, true);
    sgemm(t0, 128, Wo, bo, out, 2, GG, 2, 128, false);
}

// round 2
// speedup vs baseline: 1.4329x; 1.4329x over previous
#include <cuda_runtime.h>

#define NN 20000
#define EE 320000
#define GG 256

// -------- scratch (static device globals; no runtime allocation) --------
__device__ float g_bufA[NN * 320];
__device__ float g_bufB[NN * 320];
__device__ int   g_cnt[NN];
__device__ int   g_offs[NN + 1];
__device__ int   g_fill[NN];
__device__ int   g_csr[EE];
__device__ float g_dinv[NN];
__device__ float g_pool[GG * 312];
__device__ float g_xc[GG * 512];
__device__ float g_t0[GG * 2048];
__device__ float g_t1[GG * 2048];
__device__ float g_part[8 * GG * 1024];   // split-K partials (max S*M*N = 8*256*512 or 2*256*1024)

// -------- CSR build --------
__global__ void k_count(const int* __restrict__ dst, int* __restrict__ cnt) {
    int e = blockIdx.x * blockDim.x + threadIdx.x;
    if (e < EE) atomicAdd(&cnt[dst[e]], 1);
}

__global__ void k_dinv(const int* __restrict__ cnt, float* __restrict__ dinv) {
    int n = blockIdx.x * blockDim.x + threadIdx.x;
    if (n < NN) dinv[n] = rsqrtf((float)(cnt[n] + 1));  // +1 self loop
}

__global__ void k_scan(const int* __restrict__ cnt, int* __restrict__ offs) {
    const int T = 1024;
    const int IPT = (NN + T - 1) / T;  // 20
    __shared__ int s[T];
    int tid = threadIdx.x;
    int base = tid * IPT;
    int local = 0;
    #pragma unroll
    for (int i = 0; i < IPT; i++) {
        int idx = base + i;
        if (idx < NN) local += cnt[idx];
    }
    s[tid] = local;
    __syncthreads();
    for (int off = 1; off < T; off <<= 1) {
        int v = 0;
        if (tid >= off) v = s[tid - off];
        __syncthreads();
        if (tid >= off) s[tid] += v;
        __syncthreads();
    }
    int run = (tid == 0) ? 0 : s[tid - 1];
    #pragma unroll
    for (int i = 0; i < IPT; i++) {
        int idx = base + i;
        if (idx < NN) { offs[idx] = run; run += cnt[idx]; }
    }
    if (tid == 0) offs[NN] = s[T - 1];
}

__global__ void k_fill(const int* __restrict__ src, const int* __restrict__ dst,
                       const int* __restrict__ offs, int* __restrict__ fill,
                       int* __restrict__ csr) {
    int e = blockIdx.x * blockDim.x + threadIdx.x;
    if (e < EE) {
        int d = dst[e];
        int p = atomicAdd(&fill[d], 1);
        csr[offs[d] + p] = src[e];
    }
}

// -------- aggregation: out[n] = dinv[n] * (sum_{s in N(n)} dinv[s]*h[s] + dinv[n]*h[n])
// one warp per node, lane covers features strided by 32. LDI/LDO are row strides.
template <int DIM, int LDI, int LDO, int R>
__global__ void k_agg(const float* __restrict__ h, const int* __restrict__ offs,
                      const int* __restrict__ csr, const float* __restrict__ dinv,
                      float* __restrict__ out) {
    int warp = (blockIdx.x * blockDim.x + threadIdx.x) >> 5;
    int lane = threadIdx.x & 31;
    if (warp >= NN) return;
    int n = warp;
    float din = dinv[n];
    float acc[R];
    #pragma unroll
    for (int r = 0; r < R; r++) {
        int f = lane + 32 * r;
        acc[r] = (f < DIM) ? din * h[n * LDI + f] : 0.f;
    }
    int e0 = offs[n], e1 = offs[n + 1];
    for (int e = e0; e < e1; e++) {
        int s = csr[e];
        float ds = dinv[s];
        #pragma unroll
        for (int r = 0; r < R; r++) {
            int f = lane + 32 * r;
            if (f < DIM) acc[r] += ds * h[s * LDI + f];
        }
    }
    #pragma unroll
    for (int r = 0; r < R; r++) {
        int f = lane + 32 * r;
        if (f < DIM) out[n * LDO + f] = din * acc[r];
    }
}

// -------- global max pool --------
__global__ void k_pool(const float* __restrict__ h, const int* __restrict__ batch,
                       float* __restrict__ pool) {
    const int CH = 32;
    const int NCH = (NN + CH - 1) / CH;  // 625
    int idx = blockIdx.x * blockDim.x + threadIdx.x;
    if (idx >= NCH * 312) return;
    int f = idx % 312;
    int c = idx / 312;
    int n0 = c * CH;
    int n1 = min(n0 + CH, NN);
    int curb = batch[n0];
    float m = 0.f;
    for (int n = n0; n < n1; n++) {
        int b = batch[n];
        if (b != curb) {
            atomicMax((int*)&pool[curb * 312 + f], __float_as_int(m));
            curb = b;
            m = 0.f;
        }
        m = fmaxf(m, h[n * 312 + f]);
    }
    atomicMax((int*)&pool[curb * 312 + f], __float_as_int(m));
}

// -------- L2 row normalize --------
__global__ void k_norm(const float* __restrict__ cell, float* __restrict__ out) {
    int g = blockIdx.x;
    __shared__ float s[256];
    float ss = 0.f;
    for (int j = threadIdx.x; j < 954; j += 256) {
        float v = cell[g * 954 + j];
        ss += v * v;
    }
    s[threadIdx.x] = ss;
    __syncthreads();
    for (int o = 128; o > 0; o >>= 1) {
        if (threadIdx.x < o) s[threadIdx.x] += s[threadIdx.x + o];
        __syncthreads();
    }
    float inv = 1.f / fmaxf(sqrtf(s[0]), 1e-12f);
    for (int j = threadIdx.x; j < 954; j += 256)
        out[g * 954 + j] = cell[g * 954 + j] * inv;
}

// -------- big SGEMM: 128x64 tiles, BK=8, double-buffered. For M=20000 node GEMMs.
template <bool RELU>
__global__ __launch_bounds__(256, 3)
void k_sgemm128(const float* __restrict__ A, int lda,
                const float* __restrict__ B,
                const float* __restrict__ bias,
                float* __restrict__ C, int ldc,
                int M, int N, int K) {
    const int BM = 128, BN = 64, BK = 8;
    __shared__ float As[2][BK][BM];
    __shared__ float Bs[2][BK][BN];
    int m0 = blockIdx.y * BM;
    int n0 = blockIdx.x * BN;
    int tid = threadIdx.x;
    int tr = tid >> 4;       // 0..15 -> 8 rows each
    int tc = tid & 15;       // 0..15 -> 4 cols each

    // A load: each thread 4 elems: row am, cols ak..ak+3
    int am = tid >> 1;
    int ak = (tid & 1) * 4;
    // B load: each thread 2 elems: row bk, cols bn..bn+1
    int bk = tid >> 5;
    int bn = (tid & 31) * 2;

    int gm = m0 + am;
    const float* Arow = A + (long)min(gm, M - 1) * lda;
    bool mok = (gm < M);

    float acc[8][4] = {};

    int ktiles = (K + BK - 1) / BK;

    // prologue: load tile 0 into buffer 0
    {
        #pragma unroll
        for (int i = 0; i < 4; i++) {
            int kk = ak + i;
            As[0][kk][am] = (mok && kk < K) ? Arow[kk] : 0.f;
        }
        #pragma unroll
        for (int i = 0; i < 2; i++) {
            int nn = n0 + bn + i;
            Bs[0][bk][bn + i] = (bk < K && nn < N) ? B[bk * N + nn] : 0.f;
        }
    }
    __syncthreads();

    for (int t = 0; t < ktiles; t++) {
        int cur = t & 1;
        bool more = (t + 1 < ktiles);
        float ar[4], br[2];
        if (more) {
            int k0n = (t + 1) * BK;
            #pragma unroll
            for (int i = 0; i < 4; i++) {
                int kk = k0n + ak + i;
                ar[i] = (mok && kk < K) ? Arow[kk] : 0.f;
            }
            #pragma unroll
            for (int i = 0; i < 2; i++) {
                int kk = k0n + bk;
                int nn = n0 + bn + i;
                br[i] = (kk < K && nn < N) ? B[kk * N + nn] : 0.f;
            }
        }
        #pragma unroll
        for (int kk = 0; kk < BK; kk++) {
            float a[8], b[4];
            #pragma unroll
            for (int i = 0; i < 8; i++) a[i] = As[cur][kk][tr * 8 + i];
            #pragma unroll
            for (int j = 0; j < 4; j++) b[j] = Bs[cur][kk][tc * 4 + j];
            #pragma unroll
            for (int i = 0; i < 8; i++)
                #pragma unroll
                for (int j = 0; j < 4; j++) acc[i][j] += a[i] * b[j];
        }
        if (more) {
            int nxt = cur ^ 1;
            #pragma unroll
            for (int i = 0; i < 4; i++) As[nxt][ak + i][am] = ar[i];
            #pragma unroll
            for (int i = 0; i < 2; i++) Bs[nxt][bk][bn + i] = br[i];
            __syncthreads();
        }
    }

    #pragma unroll
    for (int i = 0; i < 8; i++) {
        int mm = m0 + tr * 8 + i;
        if (mm >= M) continue;
        #pragma unroll
        for (int j = 0; j < 4; j++) {
            int nn = n0 + tc * 4 + j;
            if (nn >= N) continue;
            float v = acc[i][j] + bias[nn];
            if (RELU) v = fmaxf(v, 0.f);
            C[(long)mm * ldc + nn] = v;
        }
    }
}

static void sgemm_big(const float* A, int lda, const float* B, const float* bias,
                      float* C, int ldc, int M, int N, int K, bool relu) {
    dim3 grid((N + 63) / 64, (M + 127) / 128);
    if (relu)
        k_sgemm128<true><<<grid, 256>>>(A, lda, B, bias, C, ldc, M, N, K);
    else
        k_sgemm128<false><<<grid, 256>>>(A, lda, B, bias, C, ldc, M, N, K);
}

// -------- small SGEMM (64x64, BK=16) with optional split-K over blockIdx.z --------
// PARTIAL: writes raw partial sums to part[s*M*N + m*N + n] for K-slice s.
template <bool RELU, bool PARTIAL>
__global__ void k_sgemm64(const float* __restrict__ A, int lda,
                          const float* __restrict__ B,
                          const float* __restrict__ bias,
                          float* __restrict__ C, int ldc,
                          int M, int N, int K, int Kc) {
    const int BM = 64, BN = 64, BK = 16;
    __shared__ float As[BK][BM];
    __shared__ float Bs[BK][BN];
    int m0 = blockIdx.y * BM;
    int n0 = blockIdx.x * BN;
    int s  = blockIdx.z;
    int kbeg = PARTIAL ? s * Kc : 0;
    int kend = PARTIAL ? min(K, kbeg + Kc) : K;
    int tid = threadIdx.x;
    int tx = tid & 15, ty = tid >> 4;
    float acc[4][4] = {};
    for (int k0 = kbeg; k0 < kend; k0 += BK) {
        #pragma unroll
        for (int i = 0; i < 4; i++) {
            int l = tid + 256 * i;
            int r = l >> 4, c = l & 15;
            int mm = m0 + r, kk = k0 + c;
            As[c][r] = (mm < M && kk < kend) ? A[mm * lda + kk] : 0.f;
        }
        #pragma unroll
        for (int i = 0; i < 4; i++) {
            int l = tid + 256 * i;
            int r = l >> 6, c = l & 63;
            int kk = k0 + r, nn = n0 + c;
            Bs[r][c] = (kk < kend && nn < N) ? B[kk * N + nn] : 0.f;
        }
        __syncthreads();
        #pragma unroll
        for (int kk = 0; kk < BK; kk++) {
            float a[4], b[4];
            #pragma unroll
            for (int i = 0; i < 4; i++) a[i] = As[kk][ty * 4 + i];
            #pragma unroll
            for (int j = 0; j < 4; j++) b[j] = Bs[kk][tx * 4 + j];
            #pragma unroll
            for (int i = 0; i < 4; i++)
                #pragma unroll
                for (int j = 0; j < 4; j++) acc[i][j] += a[i] * b[j];
        }
        __syncthreads();
    }
    #pragma unroll
    for (int i = 0; i < 4; i++) {
        int mm = m0 + ty * 4 + i;
        if (mm >= M) continue;
        #pragma unroll
        for (int j = 0; j < 4; j++) {
            int nn = n0 + tx * 4 + j;
            if (nn >= N) continue;
            if (PARTIAL) {
                C[(long)s * M * N + mm * N + nn] = acc[i][j];
            } else {
                float v = acc[i][j] + bias[nn];
                if (RELU) v = fmaxf(v, 0.f);
                C[mm * ldc + nn] = v;
            }
        }
    }
}

template <bool RELU>
__global__ void k_reduce(const float* __restrict__ part, int S,
                         const float* __restrict__ bias,
                         float* __restrict__ C, int ldc, int M, int N) {
    int i = blockIdx.x * blockDim.x + threadIdx.x;
    if (i >= M * N) return;
    int m = i / N, n = i % N;
    float v = 0.f;
    for (int s = 0; s < S; s++) v += part[(long)s * M * N + i];
    v += bias[n];
    if (RELU) v = fmaxf(v, 0.f);
    C[m * ldc + n] = v;
}

// small GEMM via split-K: partials then reduce
static void sgemm_split(const float* A, int lda, const float* B, const float* bias,
                        float* C, int ldc, int M, int N, int K, int S, bool relu,
                        float* part) {
    int Kc = (K + S - 1) / S;
    dim3 grid((N + 63) / 64, (M + 63) / 64, S);
    k_sgemm64<false, true><<<grid, 256>>>(A, lda, B, nullptr, part, 0, M, N, K, Kc);
    int tot = M * N;
    if (relu)
        k_reduce<true><<<(tot + 255) / 256, 256>>>(part, S, bias, C, ldc, M, N);
    else
        k_reduce<false><<<(tot + 255) / 256, 256>>>(part, S, bias, C, ldc, M, N);
}

static void sgemm_small(const float* A, int lda, const float* B, const float* bias,
                        float* C, int ldc, int M, int N, int K, bool relu) {
    dim3 grid((N + 63) / 64, (M + 63) / 64, 1);
    if (relu)
        k_sgemm64<true, false><<<grid, 256>>>(A, lda, B, bias, C, ldc, M, N, K, K);
    else
        k_sgemm64<false, false><<<grid, 256>>>(A, lda, B, bias, C, ldc, M, N, K, K);
}

extern "C" void kernel_launch(void* const* d_in, const int* in_sizes, int n_in,
                              void* d_out, int out_size) {
    const float* x1   = (const float*)d_in[0];
    const int*   ei1  = (const int*)d_in[1];
    const int*   bat1 = (const int*)d_in[2];
    const float* x2   = (const float*)d_in[3];
    const int*   ei2  = (const int*)d_in[4];
    const int*   bat2 = (const int*)d_in[5];
    const float* cell = (const float*)d_in[6];
    const float* Wc1 = (const float*)d_in[7];  const float* bc1 = (const float*)d_in[8];
    const float* Wc2 = (const float*)d_in[9];  const float* bc2 = (const float*)d_in[10];
    const float* Wc3 = (const float*)d_in[11]; const float* bc3 = (const float*)d_in[12];
    const float* Wg1 = (const float*)d_in[13]; const float* bg1 = (const float*)d_in[14];
    const float* Wg2 = (const float*)d_in[15]; const float* bg2 = (const float*)d_in[16];
    const float* Wr1 = (const float*)d_in[17]; const float* br1 = (const float*)d_in[18];
    const float* Wr2 = (const float*)d_in[19]; const float* br2 = (const float*)d_in[20];
    const float* Wr3 = (const float*)d_in[21]; const float* br3 = (const float*)d_in[22];
    const float* Wf1 = (const float*)d_in[23]; const float* bf1 = (const float*)d_in[24];
    const float* Wf2 = (const float*)d_in[25]; const float* bf2 = (const float*)d_in[26];
    const float* Wf3 = (const float*)d_in[27]; const float* bf3 = (const float*)d_in[28];
    const float* Wo  = (const float*)d_in[29]; const float* bo  = (const float*)d_in[30];
    float* out = (float*)d_out;

    float *bufA, *bufB, *dinv, *pool, *xc, *t0, *t1, *part;
    int *cnt, *offs, *fill, *csr;
    cudaGetSymbolAddress((void**)&bufA, g_bufA);
    cudaGetSymbolAddress((void**)&bufB, g_bufB);
    cudaGetSymbolAddress((void**)&cnt,  g_cnt);
    cudaGetSymbolAddress((void**)&offs, g_offs);
    cudaGetSymbolAddress((void**)&fill, g_fill);
    cudaGetSymbolAddress((void**)&csr,  g_csr);
    cudaGetSymbolAddress((void**)&dinv, g_dinv);
    cudaGetSymbolAddress((void**)&pool, g_pool);
    cudaGetSymbolAddress((void**)&xc,   g_xc);
    cudaGetSymbolAddress((void**)&t0,   g_t0);
    cudaGetSymbolAddress((void**)&t1,   g_t1);
    cudaGetSymbolAddress((void**)&part, g_part);

    const int EB = (EE + 255) / 256;
    const int NB = (NN + 255) / 256;
    const int AGGB = (NN * 32 + 255) / 256;  // one warp per node

    for (int br = 0; br < 2; br++) {
        const float* x     = br ? x2 : x1;
        const int*   ei    = br ? ei2 : ei1;
        const int*   batch = br ? bat2 : bat1;
        const int* src = ei;
        const int* dst = ei + EE;

        cudaMemsetAsync(cnt,  0, NN * sizeof(int));
        cudaMemsetAsync(fill, 0, NN * sizeof(int));
        k_count<<<EB, 256>>>(dst, cnt);
        k_dinv<<<NB, 256>>>(cnt, dinv);
        k_scan<<<1, 1024>>>(cnt, offs);
        k_fill<<<EB, 256>>>(src, dst, offs, fill, csr);

        // layer 1: agg(x)[N,78] (ld 78->80) then @Wc1 -> relu -> bufB [N,78] ld80
        k_agg<78, 78, 80, 3><<<AGGB, 256>>>(x, offs, csr, dinv, bufA);
        sgemm_big(bufA, 80, Wc1, bc1, bufB, 80, NN, 78, 78, true);
        // layer 2: agg(h1) ld80->80, @Wc2 -> relu -> bufB [N,156] ld160
        k_agg<78, 80, 80, 3><<<AGGB, 256>>>(bufB, offs, csr, dinv, bufA);
        sgemm_big(bufA, 80, Wc2, bc2, bufB, 160, NN, 156, 78, true);
        // layer 3: agg(h2) ld160->160, @Wc3 -> relu -> bufB [N,312] ld312
        k_agg<156, 160, 160, 5><<<AGGB, 256>>>(bufB, offs, csr, dinv, bufA);
        sgemm_big(bufA, 160, Wc3, bc3, bufB, 312, NN, 312, 156, true);

        // global max pool -> [G,312]
        cudaMemsetAsync(pool, 0, GG * 312 * sizeof(float));
        int pthreads = ((NN + 31) / 32) * 312;
        k_pool<<<(pthreads + 255) / 256, 256>>>(bufB, batch, pool);

        // branch MLP -> xc columns [br*128 .. +128)
        sgemm_split(pool, 312, Wg1, bg1, t0, 156, GG, 156, 312, 4, true, part);
        sgemm_split(t0, 156, Wg2, bg2, xc + br * 128, 512, GG, 128, 156, 2, false, part);
    }

    // cell reduction MLP -> xc columns [256..512)
    k_norm<<<GG, 256>>>(cell, t0);                        // t0: [G,954]
    sgemm_small(t0, 954, Wr1, br1, t1, 2048, GG, 2048, 954, true);
    sgemm_split(t1, 2048, Wr2, br2, t0, 512, GG, 512, 2048, 8, true, part);
    sgemm_split(t0, 512, Wr3, br3, xc + 256, 512, GG, 256, 512, 4, true, part);

    // head MLP
    sgemm_split(xc, 512, Wf1, bf1, t0, 1024, GG, 1024, 512, 2, true, part);
    sgemm_split(t0, 1024, Wf2, bf2, t1, 512, GG, 512, 1024, 4, true, part);
    sgemm_split(t1, 512, Wf3, bf3, t0, 128, GG, 128, 512, 4, true, part);
    sgemm_small(t0, 128, Wo, bo, out, 2, GG, 2, 128, false);
}